// round 6
// baseline (speedup 1.0000x reference)
#include <cuda_runtime.h>
#include <cuda_bf16.h>
#include <cstdint>
#include <math.h>

// ---------------------------------------------------------------------------
// Problem constants
// ---------------------------------------------------------------------------
static constexpr int S_ = 2048, B_ = 8, D_ = 1024, M_ = S_ * B_;
static constexpr float SCALE_ = 0.03125f;  // 1/sqrt(1024)

// ---------------------------------------------------------------------------
// Static scratch. Split-bf16 layout: row-major [rows][2*K]: hi at [k], lo at [K+k].
// ---------------------------------------------------------------------------
__device__ __nv_bfloat16 g_Qc [(size_t)M_ * 2 * D_];   // query split
__device__ __nv_bfloat16 g_Kc [(size_t)M_ * 2 * D_];   // key split
__device__ __nv_bfloat16 g_Vc [(size_t)M_ * 2 * D_];   // value split
__device__ __nv_bfloat16 g_WkT[(size_t)D_ * 2 * D_];   // Wk^T split
__device__ __nv_bfloat16 g_WqT[(size_t)D_ * 2 * D_];   // Wq^T split
__device__ __nv_bfloat16 g_WvT[(size_t)D_ * 2 * D_];   // Wv^T split
__device__ __nv_bfloat16 g_Wos[(size_t)D_ * 2 * D_];   // Wo split (row-major)
__device__ __nv_bfloat16 g_H  [(size_t)D_ * 2 * D_];   // H[b,a] = (Wq^T Wk)^T split
__device__ __nv_bfloat16 g_WvoB[(size_t)D_ * 2 * D_];  // B-layout of Wvo: C[o,a]
__device__ __nv_bfloat16 g_T  [(size_t)M_ * 2 * D_];   // T = query * G, split
__device__ float         g_Zf [(size_t)M_ * D_];       // Z = value * Wvo, fp32
__device__ __nv_bfloat16 g_Zt [(size_t)B_ * D_ * 2 * S_]; // Z^T split per batch
__device__ float         g_P  [(size_t)B_ * S_ * S_];
__device__ __nv_bfloat16 g_Pbf[(size_t)B_ * S_ * 2 * S_];
__device__ float         g_w2 [D_];                    // Wk^T * bq
__device__ float         g_cb [D_];                    // bo + Wo * bv
__device__ float         g_vb [(size_t)B_ * S_];       // key_j . w2 per (b,j)

// ---------------------------------------------------------------------------
// Portable PTX helpers
// ---------------------------------------------------------------------------
__device__ __forceinline__ uint32_t smem_u32(const void* p) {
    uint32_t a;
    asm("{ .reg .u64 t; cvta.to.shared.u64 t, %1; cvt.u32.u64 %0, t; }" : "=r"(a) : "l"(p));
    return a;
}

__device__ __forceinline__ void ldsm4(uint32_t* r, uint32_t a) {
    asm volatile("ldmatrix.sync.aligned.m8n8.x4.shared.b16 {%0,%1,%2,%3}, [%4];"
                 : "=r"(r[0]), "=r"(r[1]), "=r"(r[2]), "=r"(r[3]) : "r"(a));
}

__device__ __forceinline__ void mma16816(float* d, const uint32_t* a, const uint32_t* b) {
    asm volatile(
        "mma.sync.aligned.m16n8k16.row.col.f32.bf16.bf16.f32 "
        "{%0,%1,%2,%3}, {%4,%5,%6,%7}, {%8,%9}, {%0,%1,%2,%3};"
        : "+f"(d[0]), "+f"(d[1]), "+f"(d[2]), "+f"(d[3])
        : "r"(a[0]), "r"(a[1]), "r"(a[2]), "r"(a[3]), "r"(b[0]), "r"(b[1]));
}

__device__ __forceinline__ void cp16(uint32_t saddr, const void* gaddr) {
    asm volatile("cp.async.cg.shared.global [%0], [%1], 16;" :: "r"(saddr), "l"(gaddr));
}
__device__ __forceinline__ void cp_commit() {
    asm volatile("cp.async.commit_group;" ::: "memory");
}
template<int N>
__device__ __forceinline__ void cp_wait() {
    asm volatile("cp.async.wait_group %0;" :: "n"(N) : "memory");
}

__device__ __forceinline__ float neg_inf_f() { return __int_as_float(0xff800000); }

__device__ __forceinline__ uint32_t pack_bf2(float a, float b) {
    __nv_bfloat162 h = __floats2bfloat162_rn(a, b);
    return *reinterpret_cast<uint32_t*>(&h);
}

// ---------------------------------------------------------------------------
// Fused split GEMM body: C[m,n] = scale*(Ahi*Bhi + Alo*Bhi + Ahi*Blo) (+biases)
// CTA tile 256x128, warp tile 64x64 (8 warps), k-chunk 64, 2-stage cp.async.
// epi: 0 = fp32 out (+bias[n] if set), 1 = split-bf16 out, 4 = scores
//      (scores: v = (acc + cbias[bz*S+n]) * scale, causal mask, fp32 out)
// ---------------------------------------------------------------------------
struct GArgs {
    const __nv_bfloat16* A; const __nv_bfloat16* B;
    long lda, ldb, bsA, bsB;
    long oAlo, oBlo;
    int  Kpart;
    int  epi;
    float scale;
    const float* bias;
    const float* cbias;
    float* outF;
    __nv_bfloat16* outH;
    long ldo, bsO, loOff;
};

static constexpr int A_TILE = 32768;
static constexpr int B_TILE = 16384;
static constexpr int STAGE  = 2 * A_TILE + 2 * B_TILE;  // 96 KB
static constexpr int GEMM_SMEM = 1024 + 2 * STAGE;      // 193 KB

template<bool CAUSALK, bool TRIL>
__device__ __forceinline__ void gemm_body(const GArgs& g, int nt, int mt, int bz)
{
    if (TRIL && nt * 128 > mt * 256 + 255) return;
    const int mBase = mt * 256, nBase = nt * 128;

    extern __shared__ char smem_raw[];
    const uint32_t sbase = smem_u32(smem_raw);
    const uint32_t abase = (sbase + 1023) & ~1023u;

    const int tid  = threadIdx.x;
    const int lane = tid & 31;
    const int warp = tid >> 5;
    const int wm   = warp >> 1;
    const int wn   = warp & 1;

    const __nv_bfloat16* Ab = g.A + (long)bz * g.bsA;
    const __nv_bfloat16* Bb = g.B + (long)bz * g.bsB;

    const int kEff = CAUSALK ? (mBase + 256) : g.Kpart;
    const int nch  = kEff >> 6;

    auto issue_chunk = [&](int c) {
        const long kc = (long)(c << 6);
        const int st = c & 1;
        const uint32_t sAhi = abase + st * STAGE;
        const uint32_t sAlo = sAhi + A_TILE;
        const uint32_t sBhi = sAhi + 2 * A_TILE;
        const uint32_t sBlo = sBhi + B_TILE;
#pragma unroll
        for (int i = 0; i < 8; i++) {
            const int id = tid + i * 256;
            const int row = id >> 3, cc = id & 7;
            const uint32_t so = (uint32_t)(row << 7) + (uint32_t)((cc ^ (row & 7)) << 4);
            const __nv_bfloat16* src = Ab + (long)(mBase + row) * g.lda + kc + cc * 8;
            cp16(sAhi + so, src);
            cp16(sAlo + so, src + g.oAlo);
        }
#pragma unroll
        for (int i = 0; i < 4; i++) {
            const int id = tid + i * 256;
            const int row = id >> 3, cc = id & 7;
            const uint32_t so = (uint32_t)(row << 7) + (uint32_t)((cc ^ (row & 7)) << 4);
            const __nv_bfloat16* src = Bb + (long)(nBase + row) * g.ldb + kc + cc * 8;
            cp16(sBhi + so, src);
            cp16(sBlo + so, src + g.oBlo);
        }
        cp_commit();
    };

    float acc[4][8][4];
#pragma unroll
    for (int i = 0; i < 4; i++)
#pragma unroll
        for (int j = 0; j < 8; j++)
#pragma unroll
            for (int d = 0; d < 4; d++) acc[i][j][d] = 0.0f;

    issue_chunk(0);

    const int arow = (lane & 7) + ((lane >> 3) & 1) * 8;
    const int acol = lane >> 4;
    const int brow = (lane & 7) + ((lane >> 4) & 1) * 8;
    const int bcol = (lane >> 3) & 1;

    for (int c = 0; c < nch; c++) {
        if (c + 1 < nch) issue_chunk(c + 1);
        if (c + 1 < nch) cp_wait<1>(); else cp_wait<0>();
        __syncthreads();

        const int st = c & 1;
        const uint32_t sAhi = abase + st * STAGE;
        const uint32_t sAlo = sAhi + A_TILE;
        const uint32_t sBhi = sAhi + 2 * A_TILE;
        const uint32_t sBlo = sBhi + B_TILE;

#pragma unroll
        for (int ks = 0; ks < 4; ks++) {
            uint32_t af[4][4], bf[4][4];
            // pass 1: Alo x Bhi
#pragma unroll
            for (int mi = 0; mi < 4; mi++) {
                const int row = wm * 64 + mi * 16 + arow;
                const int cc  = ks * 2 + acol;
                ldsm4(af[mi], sAlo + (row << 7) + ((cc ^ (row & 7)) << 4));
            }
#pragma unroll
            for (int nj = 0; nj < 4; nj++) {
                const int row = wn * 64 + nj * 16 + brow;
                const int cc  = ks * 2 + bcol;
                ldsm4(bf[nj], sBhi + (row << 7) + ((cc ^ (row & 7)) << 4));
            }
#pragma unroll
            for (int mi = 0; mi < 4; mi++)
#pragma unroll
                for (int nj = 0; nj < 4; nj++) {
                    mma16816(acc[mi][2 * nj],     af[mi], &bf[nj][0]);
                    mma16816(acc[mi][2 * nj + 1], af[mi], &bf[nj][2]);
                }
            // pass 2: Ahi x Bhi
#pragma unroll
            for (int mi = 0; mi < 4; mi++) {
                const int row = wm * 64 + mi * 16 + arow;
                const int cc  = ks * 2 + acol;
                ldsm4(af[mi], sAhi + (row << 7) + ((cc ^ (row & 7)) << 4));
            }
#pragma unroll
            for (int mi = 0; mi < 4; mi++)
#pragma unroll
                for (int nj = 0; nj < 4; nj++) {
                    mma16816(acc[mi][2 * nj],     af[mi], &bf[nj][0]);
                    mma16816(acc[mi][2 * nj + 1], af[mi], &bf[nj][2]);
                }
            // pass 3: Ahi x Blo
#pragma unroll
            for (int nj = 0; nj < 4; nj++) {
                const int row = wn * 64 + nj * 16 + brow;
                const int cc  = ks * 2 + bcol;
                ldsm4(bf[nj], sBlo + (row << 7) + ((cc ^ (row & 7)) << 4));
            }
#pragma unroll
            for (int mi = 0; mi < 4; mi++)
#pragma unroll
                for (int nj = 0; nj < 4; nj++) {
                    mma16816(acc[mi][2 * nj],     af[mi], &bf[nj][0]);
                    mma16816(acc[mi][2 * nj + 1], af[mi], &bf[nj][2]);
                }
        }
        __syncthreads();
    }

    // ------------------------- epilogue -------------------------
    const int gq = lane >> 2, tg = lane & 3;
#pragma unroll
    for (int mi = 0; mi < 4; mi++) {
#pragma unroll
        for (int half = 0; half < 2; half++) {
            const int gm = mBase + wm * 64 + mi * 16 + gq + half * 8;
#pragma unroll
            for (int ni = 0; ni < 8; ni++) {
                const int gn = nBase + wn * 64 + ni * 8 + 2 * tg;
                const float v0 = acc[mi][ni][half * 2 + 0];
                const float v1 = acc[mi][ni][half * 2 + 1];

                if (g.epi == 0) {
                    float2 v;
                    v.x = v0; v.y = v1;
                    if (g.bias) { v.x += g.bias[gn + 0]; v.y += g.bias[gn + 1]; }
                    *reinterpret_cast<float2*>(
                        g.outF + (long)bz * g.bsO + (long)gm * g.ldo + gn) = v;
                } else if (g.epi == 1) {
                    float w0 = v0, w1 = v1;
                    if (g.bias) { w0 += g.bias[gn + 0]; w1 += g.bias[gn + 1]; }
                    const __nv_bfloat16 h0 = __float2bfloat16(w0);
                    const __nv_bfloat16 h1 = __float2bfloat16(w1);
                    const __nv_bfloat16 l0 = __float2bfloat16(w0 - __bfloat162float(h0));
                    const __nv_bfloat16 l1 = __float2bfloat16(w1 - __bfloat162float(h1));
                    __nv_bfloat16* o = g.outH + (long)bz * g.bsO + (long)gm * g.ldo + gn;
                    *reinterpret_cast<__nv_bfloat162*>(o) = __nv_bfloat162(h0, h1);
                    *reinterpret_cast<__nv_bfloat162*>(o + g.loOff) = __nv_bfloat162(l0, l1);
                } else {  // epi == 4 : scores with column bias
                    const float cb0 = g.cbias[(long)bz * S_ + gn + 0];
                    const float cb1 = g.cbias[(long)bz * S_ + gn + 1];
                    float2 v;
                    v.x = (gn + 0 > gm) ? neg_inf_f() : (v0 + cb0) * g.scale;
                    v.y = (gn + 1 > gm) ? neg_inf_f() : (v1 + cb1) * g.scale;
                    *reinterpret_cast<float2*>(
                        g.outF + (long)bz * g.bsO + (long)gm * g.ldo + gn) = v;
                }
            }
        }
    }
}

template<bool CAUSALK, bool TRIL>
__global__ void __launch_bounds__(256, 1) gemm_one(GArgs g)
{
    gemm_body<CAUSALK, TRIL>(g, blockIdx.x, blockIdx.y, blockIdx.z);
}

__global__ void __launch_bounds__(256, 1) gemm_dual(GArgs g0, GArgs g1)
{
    gemm_body<false, false>(blockIdx.z ? g1 : g0, blockIdx.x, blockIdx.y, 0);
}

// ---------------------------------------------------------------------------
// fp32 -> split bf16 [m][2*1024]
// ---------------------------------------------------------------------------
__global__ void conv_split_k1024(const float* __restrict__ in,
                                 __nv_bfloat16* __restrict__ out, long n4)
{
    const long i = (long)blockIdx.x * 256 + threadIdx.x;
    if (i >= n4) return;
    const float4 v = reinterpret_cast<const float4*>(in)[i];
    const long idx = i * 4;
    const long m = idx >> 10;
    const int  k = (int)(idx & 1023);

    const __nv_bfloat16 h0 = __float2bfloat16(v.x);
    const __nv_bfloat16 h1 = __float2bfloat16(v.y);
    const __nv_bfloat16 h2 = __float2bfloat16(v.z);
    const __nv_bfloat16 h3 = __float2bfloat16(v.w);
    uint2 hp, lp;
    hp.x = pack_bf2(v.x, v.y);
    hp.y = pack_bf2(v.z, v.w);
    lp.x = pack_bf2(v.x - __bfloat162float(h0), v.y - __bfloat162float(h1));
    lp.y = pack_bf2(v.z - __bfloat162float(h2), v.w - __bfloat162float(h3));

    __nv_bfloat16* o = out + m * 2048 + k;
    *reinterpret_cast<uint2*>(o)        = hp;
    *reinterpret_cast<uint2*>(o + 1024) = lp;
}

// ---------------------------------------------------------------------------
// Weight transpose + split: out[a][e](hi/lo) = W[e][a]
// ---------------------------------------------------------------------------
__global__ void transpose_split_w(const float* __restrict__ W,
                                  __nv_bfloat16* __restrict__ out)
{
    __shared__ float t[32][33];
    const int a0 = blockIdx.x * 32, e0 = blockIdx.y * 32;
    const int tx = threadIdx.x, ty = threadIdx.y;
#pragma unroll
    for (int r = 0; r < 32; r += 8)
        t[r + ty][tx] = W[(long)(e0 + r + ty) * D_ + a0 + tx];
    __syncthreads();
#pragma unroll
    for (int r = 0; r < 32; r += 8) {
        const int a = a0 + r + ty, e = e0 + tx;
        const float v = t[tx][r + ty];
        const __nv_bfloat16 h = __float2bfloat16(v);
        __nv_bfloat16* o = out + (long)a * 2 * D_ + e;
        o[0]  = h;
        o[D_] = __float2bfloat16(v - __bfloat162float(h));
    }
}

// ---------------------------------------------------------------------------
// Z fp32 [s*B+b][d] -> Zt split [b][d][hi(S)|lo(S)]
// ---------------------------------------------------------------------------
__global__ void transpose_split_v(const float* __restrict__ Vf,
                                  __nv_bfloat16* __restrict__ Vt)
{
    __shared__ float t[32][33];
    const int d0 = blockIdx.x * 32, s0 = blockIdx.y * 32, b = blockIdx.z;
    const int tx = threadIdx.x, ty = threadIdx.y;
#pragma unroll
    for (int r = 0; r < 32; r += 8)
        t[r + ty][tx] = Vf[((size_t)(s0 + r + ty) * B_ + b) * D_ + d0 + tx];
    __syncthreads();
#pragma unroll
    for (int r = 0; r < 32; r += 8) {
        const int d = d0 + r + ty, s = s0 + tx;
        const float v = t[tx][r + ty];
        const __nv_bfloat16 h = __float2bfloat16(v);
        __nv_bfloat16* o = Vt + ((size_t)b * D_ + d) * (2 * S_) + s;
        o[0]  = h;
        o[S_] = __float2bfloat16(v - __bfloat162float(h));
    }
}

// ---------------------------------------------------------------------------
// Small exact-bias kernels
// ---------------------------------------------------------------------------
__global__ void w2_kernel(const float* __restrict__ Wk, const float* __restrict__ bq,
                          float* __restrict__ w2)
{
    const int a = blockIdx.x * 256 + threadIdx.x;
    float s = 0.0f;
    for (int d = 0; d < D_; d++) s += bq[d] * Wk[(long)d * D_ + a];
    w2[a] = s;
}

__global__ void cb_kernel(const float* __restrict__ Wo, const float* __restrict__ bv,
                          const float* __restrict__ bo, float* __restrict__ cb)
{
    const int o = blockIdx.x * 8 + (threadIdx.x >> 5);
    const int lane = threadIdx.x & 31;
    float s = 0.0f;
    for (int e = lane * 4; e < D_; e += 128) {
        const float4 w = *reinterpret_cast<const float4*>(Wo + (long)o * D_ + e);
        const float4 b = *reinterpret_cast<const float4*>(bv + e);
        s += w.x * b.x + w.y * b.y + w.z * b.z + w.w * b.w;
    }
#pragma unroll
    for (int off = 16; off > 0; off >>= 1) s += __shfl_xor_sync(0xffffffffu, s, off);
    if (lane == 0) cb[o] = bo[o] + s;
}

__global__ void vb_kernel(const float* __restrict__ key, const float* __restrict__ w2,
                          float* __restrict__ vb)
{
    const int m = blockIdx.x * 8 + (threadIdx.x >> 5);
    const int lane = threadIdx.x & 31;
    const float* row = key + (long)m * D_;
    float s = 0.0f;
    for (int a = lane * 4; a < D_; a += 128) {
        const float4 k = *reinterpret_cast<const float4*>(row + a);
        const float4 w = *reinterpret_cast<const float4*>(w2 + a);
        s += k.x * w.x + k.y * w.y + k.z * w.z + k.w * w.w;
    }
#pragma unroll
    for (int off = 16; off > 0; off >>= 1) s += __shfl_xor_sync(0xffffffffu, s, off);
    if (lane == 0) {
        const int b = m & (B_ - 1);
        const int j = m >> 3;
        vb[(long)b * S_ + j] = s;
    }
}

// ---------------------------------------------------------------------------
// Fused row softmax + split-bf16 emit
// ---------------------------------------------------------------------------
__global__ void __launch_bounds__(256) softmax_split(const float* __restrict__ P,
                                                     __nv_bfloat16* __restrict__ Pb)
{
    const int i = blockIdx.x, b = blockIdx.y;
    const float* p = P + ((size_t)b * S_ + i) * S_;
    __nv_bfloat16* o = Pb + ((size_t)b * S_ + i) * (2 * S_);
    const int jEnd = ((i >> 7) + 1) << 7;
    const int tid = threadIdx.x;
    __shared__ float sm[8];

    float m = neg_inf_f();
    for (int j = tid * 2; j < jEnd; j += 512) {
        const float2 v = *reinterpret_cast<const float2*>(p + j);
        m = fmaxf(m, fmaxf(v.x, v.y));
    }
#pragma unroll
    for (int off = 16; off > 0; off >>= 1) m = fmaxf(m, __shfl_xor_sync(0xffffffffu, m, off));
    if ((tid & 31) == 0) sm[tid >> 5] = m;
    __syncthreads();
    const float rowmax = fmaxf(fmaxf(fmaxf(sm[0], sm[1]), fmaxf(sm[2], sm[3])),
                               fmaxf(fmaxf(sm[4], sm[5]), fmaxf(sm[6], sm[7])));
    __syncthreads();

    float s = 0.0f;
    for (int j = tid * 2; j < jEnd; j += 512) {
        const float2 v = *reinterpret_cast<const float2*>(p + j);
        s += expf(v.x - rowmax) + expf(v.y - rowmax);
    }
#pragma unroll
    for (int off = 16; off > 0; off >>= 1) s += __shfl_xor_sync(0xffffffffu, s, off);
    if ((tid & 31) == 0) sm[tid >> 5] = s;
    __syncthreads();
    const float inv = 1.0f / ((sm[0] + sm[1]) + (sm[2] + sm[3]) + (sm[4] + sm[5]) + (sm[6] + sm[7]));

    for (int j = tid * 2; j < jEnd; j += 512) {
        const float2 v = *reinterpret_cast<const float2*>(p + j);
        const float e0 = expf(v.x - rowmax) * inv;
        const float e1 = expf(v.y - rowmax) * inv;
        const __nv_bfloat16 h0 = __float2bfloat16(e0);
        const __nv_bfloat16 h1 = __float2bfloat16(e1);
        *reinterpret_cast<uint32_t*>(o + j) = pack_bf2(e0, e1);
        *reinterpret_cast<uint32_t*>(o + S_ + j) =
            pack_bf2(e0 - __bfloat162float(h0), e1 - __bfloat162float(h1));
    }
}

// ---------------------------------------------------------------------------
extern "C" void kernel_launch(void* const* d_in, const int* in_sizes, int n_in,
                              void* d_out, int out_size)
{
    const float* query = (const float*)d_in[0];
    const float* key   = (const float*)d_in[1];
    const float* value = (const float*)d_in[2];
    const float* Wq = (const float*)d_in[4];
    const float* bq = (const float*)d_in[5];
    const float* Wk = (const float*)d_in[6];
    // d_in[7] = bk : only enters via softmax-invariant terms -> dropped exactly
    const float* Wv = (const float*)d_in[8];
    const float* bv = (const float*)d_in[9];
    const float* Wo = (const float*)d_in[10];
    const float* bo = (const float*)d_in[11];
    float* out = (float*)d_out;

    __nv_bfloat16 *Qc, *Kc, *Vc, *WkT, *WqT, *WvT, *Wos, *H, *WvoB, *T, *Zt, *Pbf;
    float *Zf, *P, *w2, *cb, *vb;
    cudaGetSymbolAddress((void**)&Qc,  g_Qc);
    cudaGetSymbolAddress((void**)&Kc,  g_Kc);
    cudaGetSymbolAddress((void**)&Vc,  g_Vc);
    cudaGetSymbolAddress((void**)&WkT, g_WkT);
    cudaGetSymbolAddress((void**)&WqT, g_WqT);
    cudaGetSymbolAddress((void**)&WvT, g_WvT);
    cudaGetSymbolAddress((void**)&Wos, g_Wos);
    cudaGetSymbolAddress((void**)&H,   g_H);
    cudaGetSymbolAddress((void**)&WvoB,g_WvoB);
    cudaGetSymbolAddress((void**)&T,   g_T);
    cudaGetSymbolAddress((void**)&Zf,  g_Zf);
    cudaGetSymbolAddress((void**)&Zt,  g_Zt);
    cudaGetSymbolAddress((void**)&P,   g_P);
    cudaGetSymbolAddress((void**)&Pbf, g_Pbf);
    cudaGetSymbolAddress((void**)&w2,  g_w2);
    cudaGetSymbolAddress((void**)&cb,  g_cb);
    cudaGetSymbolAddress((void**)&vb,  g_vb);

    cudaFuncSetAttribute(gemm_dual,
                         cudaFuncAttributeMaxDynamicSharedMemorySize, GEMM_SMEM);
    cudaFuncSetAttribute(gemm_one<false, true>,
                         cudaFuncAttributeMaxDynamicSharedMemorySize, GEMM_SMEM);
    cudaFuncSetAttribute(gemm_one<true, false>,
                         cudaFuncAttributeMaxDynamicSharedMemorySize, GEMM_SMEM);

    const long n4w = (long)D_ * D_ / 4;
    const long n4i = (long)M_ * D_ / 4;

    // ---- conversions ----
    conv_split_k1024<<<(unsigned)((n4i + 255) / 256), 256>>>(query, Qc, n4i);
    conv_split_k1024<<<(unsigned)((n4i + 255) / 256), 256>>>(key,   Kc, n4i);
    conv_split_k1024<<<(unsigned)((n4i + 255) / 256), 256>>>(value, Vc, n4i);
    conv_split_k1024<<<(unsigned)((n4w + 255) / 256), 256>>>(Wo, Wos, n4w);
    transpose_split_w<<<dim3(D_ / 32, D_ / 32), dim3(32, 8)>>>(Wk, WkT);
    transpose_split_w<<<dim3(D_ / 32, D_ / 32), dim3(32, 8)>>>(Wq, WqT);
    transpose_split_w<<<dim3(D_ / 32, D_ / 32), dim3(32, 8)>>>(Wv, WvT);

    // ---- exact bias terms ----
    w2_kernel<<<D_ / 256, 256>>>(Wk, bq, w2);
    cb_kernel<<<D_ / 8, 256>>>(Wo, bv, bo, cb);
    vb_kernel<<<M_ / 8, 256>>>(key, w2, vb);

    // ---- H = (Wq^T Wk)^T  and  WvoB[o][a] = (Wo Wv)[o? ] combined weights ----
    GArgs hA{};
    hA.A = WkT; hA.lda = 2 * D_; hA.bsA = 0; hA.oAlo = D_;
    hA.B = WqT; hA.ldb = 2 * D_; hA.bsB = 0; hA.oBlo = D_;
    hA.Kpart = D_; hA.epi = 1; hA.scale = 1.0f; hA.bias = nullptr; hA.cbias = nullptr;
    hA.outH = H; hA.ldo = 2 * D_; hA.bsO = 0; hA.loOff = D_;
    GArgs hB = hA;
    hB.A = Wos; hB.B = WvT; hB.outH = WvoB;
    gemm_dual<<<dim3(D_ / 128, D_ / 256, 2), 256, GEMM_SMEM>>>(hA, hB);

    // ---- T = query * G (split out)  and  Z = value * Wvo (fp32 out) ----
    GArgs tA{};
    tA.A = Qc; tA.lda = 2 * D_; tA.bsA = 0; tA.oAlo = D_;
    tA.B = H;  tA.ldb = 2 * D_; tA.bsB = 0; tA.oBlo = D_;
    tA.Kpart = D_; tA.epi = 1; tA.scale = 1.0f; tA.bias = nullptr; tA.cbias = nullptr;
    tA.outH = T; tA.ldo = 2 * D_; tA.bsO = 0; tA.loOff = D_;
    GArgs tB = tA;
    tB.A = Vc; tB.B = WvoB; tB.epi = 0; tB.outH = nullptr;
    tB.outF = Zf; tB.ldo = D_;
    gemm_dual<<<dim3(D_ / 128, M_ / 256, 2), 256, GEMM_SMEM>>>(tA, tB);

    // ---- Z^T split for the PV GEMM ----
    transpose_split_v<<<dim3(D_ / 32, S_ / 32, B_), dim3(32, 8)>>>(Zf, Zt);

    // ---- Scores: P = SCALE * (T . key^T + vb), tril tiles, causal mask ----
    GArgs sc{};
    sc.A = T;  sc.lda = (long)B_ * 2 * D_; sc.bsA = 2 * D_; sc.oAlo = D_;
    sc.B = Kc; sc.ldb = (long)B_ * 2 * D_; sc.bsB = 2 * D_; sc.oBlo = D_;
    sc.Kpart = D_; sc.epi = 4; sc.scale = SCALE_; sc.bias = nullptr; sc.cbias = vb;
    sc.outF = P; sc.ldo = S_; sc.bsO = (long)S_ * S_;
    gemm_one<false, true><<<dim3(S_ / 128, S_ / 256, B_), 256, GEMM_SMEM>>>(sc);

    // ---- fused softmax + P split ----
    softmax_split<<<dim3(S_, B_), 256>>>(P, Pbf);

    // ---- out = P @ Z + cb (causal K bound), fp32 straight to d_out ----
    GArgs pv{};
    pv.A = Pbf; pv.lda = 2 * S_; pv.bsA = (long)S_ * 2 * S_; pv.oAlo = S_;
    pv.B = Zt;  pv.ldb = 2 * S_; pv.bsB = (long)D_ * 2 * S_; pv.oBlo = S_;
    pv.Kpart = S_; pv.epi = 0; pv.scale = 1.0f; pv.bias = cb; pv.cbias = nullptr;
    pv.outF = out; pv.ldo = (long)B_ * D_; pv.bsO = D_;
    gemm_one<true, false><<<dim3(D_ / 128, S_ / 256, B_), 256, GEMM_SMEM>>>(pv);
}

// round 9
// speedup vs baseline: 1.4432x; 1.4432x over previous
#include <cuda_runtime.h>
#include <cuda_bf16.h>
#include <cstdint>
#include <math.h>

// ---------------------------------------------------------------------------
// Problem constants
// ---------------------------------------------------------------------------
static constexpr int S_ = 2048, B_ = 8, D_ = 1024, M_ = S_ * B_;
static constexpr float SCALE_ = 0.03125f;  // 1/sqrt(1024)

// ---------------------------------------------------------------------------
// Static scratch. Split-bf16 layout: row-major [rows][2*K]: hi at [k], lo at [K+k].
// ---------------------------------------------------------------------------
__device__ __nv_bfloat16 g_Qc [(size_t)M_ * 2 * D_];   // query split
__device__ __nv_bfloat16 g_Kc [(size_t)M_ * 2 * D_];   // key split
__device__ __nv_bfloat16 g_Vc [(size_t)M_ * 2 * D_];   // value split
__device__ __nv_bfloat16 g_WkT[(size_t)D_ * 2 * D_];   // Wk^T split
__device__ __nv_bfloat16 g_WqT[(size_t)D_ * 2 * D_];   // Wq^T split
__device__ __nv_bfloat16 g_WvT[(size_t)D_ * 2 * D_];   // Wv^T split
__device__ __nv_bfloat16 g_Wos[(size_t)D_ * 2 * D_];   // Wo split (row-major)
__device__ __nv_bfloat16 g_H  [(size_t)D_ * 2 * D_];   // (Wk^T Wq) split, rows=a
__device__ __nv_bfloat16 g_WvoB[(size_t)D_ * 2 * D_];  // (Wo Wv)[o][a] split
__device__ __nv_bfloat16 g_T  [(size_t)M_ * 2 * D_];   // T = query * G, split
__device__ float         g_Zf [(size_t)M_ * D_];       // Z = value * Wvo^T, fp32
__device__ __nv_bfloat16 g_Zt [(size_t)B_ * D_ * 2 * S_]; // Z^T split per batch
__device__ float         g_P  [(size_t)B_ * S_ * S_];
__device__ __nv_bfloat16 g_Pbf[(size_t)B_ * S_ * 2 * S_];
__device__ float         g_w2 [D_];                    // Wk^T * bq
__device__ float         g_cb [D_];                    // bo + Wo * bv
__device__ float         g_vb [(size_t)B_ * S_];       // key_j . w2 per (b,j)

// ---------------------------------------------------------------------------
// Portable PTX helpers
// ---------------------------------------------------------------------------
__device__ __forceinline__ uint32_t smem_u32(const void* p) {
    uint32_t a;
    asm("{ .reg .u64 t; cvta.to.shared.u64 t, %1; cvt.u32.u64 %0, t; }" : "=r"(a) : "l"(p));
    return a;
}

__device__ __forceinline__ void ldsm4(uint32_t* r, uint32_t a) {
    asm volatile("ldmatrix.sync.aligned.m8n8.x4.shared.b16 {%0,%1,%2,%3}, [%4];"
                 : "=r"(r[0]), "=r"(r[1]), "=r"(r[2]), "=r"(r[3]) : "r"(a));
}

__device__ __forceinline__ void mma16816(float* d, const uint32_t* a, const uint32_t* b) {
    asm volatile(
        "mma.sync.aligned.m16n8k16.row.col.f32.bf16.bf16.f32 "
        "{%0,%1,%2,%3}, {%4,%5,%6,%7}, {%8,%9}, {%0,%1,%2,%3};"
        : "+f"(d[0]), "+f"(d[1]), "+f"(d[2]), "+f"(d[3])
        : "r"(a[0]), "r"(a[1]), "r"(a[2]), "r"(a[3]), "r"(b[0]), "r"(b[1]));
}

__device__ __forceinline__ void cp16(uint32_t saddr, const void* gaddr) {
    asm volatile("cp.async.cg.shared.global [%0], [%1], 16;" :: "r"(saddr), "l"(gaddr));
}
__device__ __forceinline__ void cp_commit() {
    asm volatile("cp.async.commit_group;" ::: "memory");
}
template<int N>
__device__ __forceinline__ void cp_wait() {
    asm volatile("cp.async.wait_group %0;" :: "n"(N) : "memory");
}

__device__ __forceinline__ float neg_inf_f() { return __int_as_float(0xff800000); }

__device__ __forceinline__ uint32_t pack_bf2(float a, float b) {
    __nv_bfloat162 h = __floats2bfloat162_rn(a, b);
    return *reinterpret_cast<uint32_t*>(&h);
}

// ---------------------------------------------------------------------------
// Fused split GEMM body: C[m,n] = scale*(Ahi*Bhi + Alo*Bhi + Ahi*Blo) (+biases)
// CTA tile 256x128, warp tile 64x64 (8 warps), k-chunk 64, 2-stage cp.async.
// EPI (compile time): 0 = fp32 out (+bias[n] if non-null), 1 = split-bf16 out,
//                     4 = scores: v = (acc + cbias[bz*S+n]) * scale, causal mask
// ---------------------------------------------------------------------------
struct GArgs {
    const __nv_bfloat16* A; const __nv_bfloat16* B;
    long lda, ldb, bsA, bsB;
    long oAlo, oBlo;
    int  Kpart;
    float scale;
    const float* bias;
    const float* cbias;
    float* outF;
    __nv_bfloat16* outH;
    long ldo, bsO, loOff;
};

static constexpr int A_TILE = 32768;
static constexpr int B_TILE = 16384;
static constexpr int STAGE  = 2 * A_TILE + 2 * B_TILE;  // 96 KB
static constexpr int GEMM_SMEM = 1024 + 2 * STAGE;      // 193 KB

template<int EPI, bool CAUSALK, bool TRIL>
__device__ __forceinline__ void gemm_body(const GArgs& g, int nt, int mt, int bz)
{
    if (TRIL && nt * 128 > mt * 256 + 255) return;
    const int mBase = mt * 256, nBase = nt * 128;

    extern __shared__ char smem_raw[];
    const uint32_t sbase = smem_u32(smem_raw);
    const uint32_t abase = (sbase + 1023) & ~1023u;

    const int tid  = threadIdx.x;
    const int lane = tid & 31;
    const int warp = tid >> 5;
    const int wm   = warp >> 1;
    const int wn   = warp & 1;

    const __nv_bfloat16* Ab = g.A + (long)bz * g.bsA;
    const __nv_bfloat16* Bb = g.B + (long)bz * g.bsB;

    const int kEff = CAUSALK ? (mBase + 256) : g.Kpart;
    const int nch  = kEff >> 6;

    auto issue_chunk = [&](int c) {
        const long kc = (long)(c << 6);
        const int st = c & 1;
        const uint32_t sAhi = abase + st * STAGE;
        const uint32_t sAlo = sAhi + A_TILE;
        const uint32_t sBhi = sAhi + 2 * A_TILE;
        const uint32_t sBlo = sBhi + B_TILE;
#pragma unroll
        for (int i = 0; i < 8; i++) {
            const int id = tid + i * 256;
            const int row = id >> 3, cc = id & 7;
            const uint32_t so = (uint32_t)(row << 7) + (uint32_t)((cc ^ (row & 7)) << 4);
            const __nv_bfloat16* src = Ab + (long)(mBase + row) * g.lda + kc + cc * 8;
            cp16(sAhi + so, src);
            cp16(sAlo + so, src + g.oAlo);
        }
#pragma unroll
        for (int i = 0; i < 4; i++) {
            const int id = tid + i * 256;
            const int row = id >> 3, cc = id & 7;
            const uint32_t so = (uint32_t)(row << 7) + (uint32_t)((cc ^ (row & 7)) << 4);
            const __nv_bfloat16* src = Bb + (long)(nBase + row) * g.ldb + kc + cc * 8;
            cp16(sBhi + so, src);
            cp16(sBlo + so, src + g.oBlo);
        }
        cp_commit();
    };

    float acc[4][8][4];
#pragma unroll
    for (int i = 0; i < 4; i++)
#pragma unroll
        for (int j = 0; j < 8; j++)
#pragma unroll
            for (int d = 0; d < 4; d++) acc[i][j][d] = 0.0f;

    issue_chunk(0);

    const int arow = (lane & 7) + ((lane >> 3) & 1) * 8;
    const int acol = lane >> 4;
    const int brow = (lane & 7) + ((lane >> 4) & 1) * 8;
    const int bcol = (lane >> 3) & 1;

    for (int c = 0; c < nch; c++) {
        if (c + 1 < nch) issue_chunk(c + 1);
        if (c + 1 < nch) cp_wait<1>(); else cp_wait<0>();
        __syncthreads();

        const int st = c & 1;
        const uint32_t sAhi = abase + st * STAGE;
        const uint32_t sAlo = sAhi + A_TILE;
        const uint32_t sBhi = sAhi + 2 * A_TILE;
        const uint32_t sBlo = sBhi + B_TILE;

#pragma unroll
        for (int ks = 0; ks < 4; ks++) {
            uint32_t af[4][4], bf[4][4];
            // pass 1: Alo x Bhi
#pragma unroll
            for (int mi = 0; mi < 4; mi++) {
                const int row = wm * 64 + mi * 16 + arow;
                const int cc  = ks * 2 + acol;
                ldsm4(af[mi], sAlo + (row << 7) + ((cc ^ (row & 7)) << 4));
            }
#pragma unroll
            for (int nj = 0; nj < 4; nj++) {
                const int row = wn * 64 + nj * 16 + brow;
                const int cc  = ks * 2 + bcol;
                ldsm4(bf[nj], sBhi + (row << 7) + ((cc ^ (row & 7)) << 4));
            }
#pragma unroll
            for (int mi = 0; mi < 4; mi++)
#pragma unroll
                for (int nj = 0; nj < 4; nj++) {
                    mma16816(acc[mi][2 * nj],     af[mi], &bf[nj][0]);
                    mma16816(acc[mi][2 * nj + 1], af[mi], &bf[nj][2]);
                }
            // pass 2: Ahi x Bhi
#pragma unroll
            for (int mi = 0; mi < 4; mi++) {
                const int row = wm * 64 + mi * 16 + arow;
                const int cc  = ks * 2 + acol;
                ldsm4(af[mi], sAhi + (row << 7) + ((cc ^ (row & 7)) << 4));
            }
#pragma unroll
            for (int mi = 0; mi < 4; mi++)
#pragma unroll
                for (int nj = 0; nj < 4; nj++) {
                    mma16816(acc[mi][2 * nj],     af[mi], &bf[nj][0]);
                    mma16816(acc[mi][2 * nj + 1], af[mi], &bf[nj][2]);
                }
            // pass 3: Ahi x Blo
#pragma unroll
            for (int nj = 0; nj < 4; nj++) {
                const int row = wn * 64 + nj * 16 + brow;
                const int cc  = ks * 2 + bcol;
                ldsm4(bf[nj], sBlo + (row << 7) + ((cc ^ (row & 7)) << 4));
            }
#pragma unroll
            for (int mi = 0; mi < 4; mi++)
#pragma unroll
                for (int nj = 0; nj < 4; nj++) {
                    mma16816(acc[mi][2 * nj],     af[mi], &bf[nj][0]);
                    mma16816(acc[mi][2 * nj + 1], af[mi], &bf[nj][2]);
                }
        }
        __syncthreads();
    }

    // ------------------------- epilogue (compile-time EPI) -------------------
    const int gq = lane >> 2, tg = lane & 3;
#pragma unroll
    for (int mi = 0; mi < 4; mi++) {
#pragma unroll
        for (int half = 0; half < 2; half++) {
            const int gm = mBase + wm * 64 + mi * 16 + gq + half * 8;
#pragma unroll
            for (int ni = 0; ni < 8; ni++) {
                const int gn = nBase + wn * 64 + ni * 8 + 2 * tg;
                const float v0 = acc[mi][ni][half * 2 + 0];
                const float v1 = acc[mi][ni][half * 2 + 1];

                if (EPI == 0) {
                    float2 v;
                    v.x = v0; v.y = v1;
                    if (g.bias) { v.x += g.bias[gn + 0]; v.y += g.bias[gn + 1]; }
                    *reinterpret_cast<float2*>(
                        g.outF + (long)bz * g.bsO + (long)gm * g.ldo + gn) = v;
                } else if (EPI == 1) {
                    const float w0 = v0, w1 = v1;
                    const __nv_bfloat16 h0 = __float2bfloat16(w0);
                    const __nv_bfloat16 h1 = __float2bfloat16(w1);
                    const __nv_bfloat16 l0 = __float2bfloat16(w0 - __bfloat162float(h0));
                    const __nv_bfloat16 l1 = __float2bfloat16(w1 - __bfloat162float(h1));
                    __nv_bfloat16* o = g.outH + (long)bz * g.bsO + (long)gm * g.ldo + gn;
                    *reinterpret_cast<__nv_bfloat162*>(o) = __nv_bfloat162(h0, h1);
                    *reinterpret_cast<__nv_bfloat162*>(o + g.loOff) = __nv_bfloat162(l0, l1);
                } else {  // EPI == 4 : scores with column bias + causal mask
                    const float cb0 = g.cbias[(long)bz * S_ + gn + 0];
                    const float cb1 = g.cbias[(long)bz * S_ + gn + 1];
                    float2 v;
                    v.x = (gn + 0 > gm) ? neg_inf_f() : (v0 + cb0) * g.scale;
                    v.y = (gn + 1 > gm) ? neg_inf_f() : (v1 + cb1) * g.scale;
                    *reinterpret_cast<float2*>(
                        g.outF + (long)bz * g.bsO + (long)gm * g.ldo + gn) = v;
                }
            }
        }
    }
}

template<int EPI, bool CAUSALK, bool TRIL>
__global__ void __launch_bounds__(256, 1) gemm_one(GArgs g)
{
    gemm_body<EPI, CAUSALK, TRIL>(g, blockIdx.x, blockIdx.y, blockIdx.z);
}

// Two EPI=1 GEMMs in one launch (same code path; z picks the arg set).
__global__ void __launch_bounds__(256, 1) gemm_dual1(GArgs g0, GArgs g1)
{
    gemm_body<1, false, false>(blockIdx.z ? g1 : g0, blockIdx.x, blockIdx.y, 0);
}

// ---------------------------------------------------------------------------
// fp32 -> split bf16 [m][2*1024]
// ---------------------------------------------------------------------------
__global__ void conv_split_k1024(const float* __restrict__ in,
                                 __nv_bfloat16* __restrict__ out, long n4)
{
    const long i = (long)blockIdx.x * 256 + threadIdx.x;
    if (i >= n4) return;
    const float4 v = reinterpret_cast<const float4*>(in)[i];
    const long idx = i * 4;
    const long m = idx >> 10;
    const int  k = (int)(idx & 1023);

    const __nv_bfloat16 h0 = __float2bfloat16(v.x);
    const __nv_bfloat16 h1 = __float2bfloat16(v.y);
    const __nv_bfloat16 h2 = __float2bfloat16(v.z);
    const __nv_bfloat16 h3 = __float2bfloat16(v.w);
    uint2 hp, lp;
    hp.x = pack_bf2(v.x, v.y);
    hp.y = pack_bf2(v.z, v.w);
    lp.x = pack_bf2(v.x - __bfloat162float(h0), v.y - __bfloat162float(h1));
    lp.y = pack_bf2(v.z - __bfloat162float(h2), v.w - __bfloat162float(h3));

    __nv_bfloat16* o = out + m * 2048 + k;
    *reinterpret_cast<uint2*>(o)        = hp;
    *reinterpret_cast<uint2*>(o + 1024) = lp;
}

// ---------------------------------------------------------------------------
// Weight transpose + split: out[a][e](hi/lo) = W[e][a]
// ---------------------------------------------------------------------------
__global__ void transpose_split_w(const float* __restrict__ W,
                                  __nv_bfloat16* __restrict__ out)
{
    __shared__ float t[32][33];
    const int a0 = blockIdx.x * 32, e0 = blockIdx.y * 32;
    const int tx = threadIdx.x, ty = threadIdx.y;
#pragma unroll
    for (int r = 0; r < 32; r += 8)
        t[r + ty][tx] = W[(long)(e0 + r + ty) * D_ + a0 + tx];
    __syncthreads();
#pragma unroll
    for (int r = 0; r < 32; r += 8) {
        const int a = a0 + r + ty, e = e0 + tx;
        const float v = t[tx][r + ty];
        const __nv_bfloat16 h = __float2bfloat16(v);
        __nv_bfloat16* o = out + (long)a * 2 * D_ + e;
        o[0]  = h;
        o[D_] = __float2bfloat16(v - __bfloat162float(h));
    }
}

// ---------------------------------------------------------------------------
// Z fp32 [s*B+b][d] -> Zt split [b][d][hi(S)|lo(S)]
// ---------------------------------------------------------------------------
__global__ void transpose_split_v(const float* __restrict__ Vf,
                                  __nv_bfloat16* __restrict__ Vt)
{
    __shared__ float t[32][33];
    const int d0 = blockIdx.x * 32, s0 = blockIdx.y * 32, b = blockIdx.z;
    const int tx = threadIdx.x, ty = threadIdx.y;
#pragma unroll
    for (int r = 0; r < 32; r += 8)
        t[r + ty][tx] = Vf[((size_t)(s0 + r + ty) * B_ + b) * D_ + d0 + tx];
    __syncthreads();
#pragma unroll
    for (int r = 0; r < 32; r += 8) {
        const int d = d0 + r + ty, s = s0 + tx;
        const float v = t[tx][r + ty];
        const __nv_bfloat16 h = __float2bfloat16(v);
        __nv_bfloat16* o = Vt + ((size_t)b * D_ + d) * (2 * S_) + s;
        o[0]  = h;
        o[S_] = __float2bfloat16(v - __bfloat162float(h));
    }
}

// ---------------------------------------------------------------------------
// Small exact-bias kernels
// ---------------------------------------------------------------------------
__global__ void w2_kernel(const float* __restrict__ Wk, const float* __restrict__ bq,
                          float* __restrict__ w2)
{
    const int a = blockIdx.x * 256 + threadIdx.x;
    float s = 0.0f;
    for (int d = 0; d < D_; d++) s += bq[d] * Wk[(long)d * D_ + a];
    w2[a] = s;
}

__global__ void cb_kernel(const float* __restrict__ Wo, const float* __restrict__ bv,
                          const float* __restrict__ bo, float* __restrict__ cb)
{
    const int o = blockIdx.x * 8 + (threadIdx.x >> 5);
    const int lane = threadIdx.x & 31;
    float s = 0.0f;
    for (int e = lane * 4; e < D_; e += 128) {
        const float4 w = *reinterpret_cast<const float4*>(Wo + (long)o * D_ + e);
        const float4 b = *reinterpret_cast<const float4*>(bv + e);
        s += w.x * b.x + w.y * b.y + w.z * b.z + w.w * b.w;
    }
#pragma unroll
    for (int off = 16; off > 0; off >>= 1) s += __shfl_xor_sync(0xffffffffu, s, off);
    if (lane == 0) cb[o] = bo[o] + s;
}

__global__ void vb_kernel(const float* __restrict__ key, const float* __restrict__ w2,
                          float* __restrict__ vb)
{
    const int m = blockIdx.x * 8 + (threadIdx.x >> 5);
    const int lane = threadIdx.x & 31;
    const float* row = key + (long)m * D_;
    float s = 0.0f;
    for (int a = lane * 4; a < D_; a += 128) {
        const float4 k = *reinterpret_cast<const float4*>(row + a);
        const float4 w = *reinterpret_cast<const float4*>(w2 + a);
        s += k.x * w.x + k.y * w.y + k.z * w.z + k.w * w.w;
    }
#pragma unroll
    for (int off = 16; off > 0; off >>= 1) s += __shfl_xor_sync(0xffffffffu, s, off);
    if (lane == 0) {
        const int b = m & (B_ - 1);
        const int j = m >> 3;
        vb[(long)b * S_ + j] = s;
    }
}

// ---------------------------------------------------------------------------
// Fused row softmax + split-bf16 emit
// ---------------------------------------------------------------------------
__global__ void __launch_bounds__(256) softmax_split(const float* __restrict__ P,
                                                     __nv_bfloat16* __restrict__ Pb)
{
    const int i = blockIdx.x, b = blockIdx.y;
    const float* p = P + ((size_t)b * S_ + i) * S_;
    __nv_bfloat16* o = Pb + ((size_t)b * S_ + i) * (2 * S_);
    const int jEnd = ((i >> 7) + 1) << 7;
    const int tid = threadIdx.x;
    __shared__ float sm[8];

    float m = neg_inf_f();
    for (int j = tid * 2; j < jEnd; j += 512) {
        const float2 v = *reinterpret_cast<const float2*>(p + j);
        m = fmaxf(m, fmaxf(v.x, v.y));
    }
#pragma unroll
    for (int off = 16; off > 0; off >>= 1) m = fmaxf(m, __shfl_xor_sync(0xffffffffu, m, off));
    if ((tid & 31) == 0) sm[tid >> 5] = m;
    __syncthreads();
    const float rowmax = fmaxf(fmaxf(fmaxf(sm[0], sm[1]), fmaxf(sm[2], sm[3])),
                               fmaxf(fmaxf(sm[4], sm[5]), fmaxf(sm[6], sm[7])));
    __syncthreads();

    float s = 0.0f;
    for (int j = tid * 2; j < jEnd; j += 512) {
        const float2 v = *reinterpret_cast<const float2*>(p + j);
        s += expf(v.x - rowmax) + expf(v.y - rowmax);
    }
#pragma unroll
    for (int off = 16; off > 0; off >>= 1) s += __shfl_xor_sync(0xffffffffu, s, off);
    if ((tid & 31) == 0) sm[tid >> 5] = s;
    __syncthreads();
    const float inv = 1.0f / ((sm[0] + sm[1]) + (sm[2] + sm[3]) + (sm[4] + sm[5]) + (sm[6] + sm[7]));

    for (int j = tid * 2; j < jEnd; j += 512) {
        const float2 v = *reinterpret_cast<const float2*>(p + j);
        const float e0 = expf(v.x - rowmax) * inv;
        const float e1 = expf(v.y - rowmax) * inv;
        const __nv_bfloat16 h0 = __float2bfloat16(e0);
        const __nv_bfloat16 h1 = __float2bfloat16(e1);
        *reinterpret_cast<uint32_t*>(o + j) = pack_bf2(e0, e1);
        *reinterpret_cast<uint32_t*>(o + S_ + j) =
            pack_bf2(e0 - __bfloat162float(h0), e1 - __bfloat162float(h1));
    }
}

// ---------------------------------------------------------------------------
extern "C" void kernel_launch(void* const* d_in, const int* in_sizes, int n_in,
                              void* d_out, int out_size)
{
    const float* query = (const float*)d_in[0];
    const float* key   = (const float*)d_in[1];
    const float* value = (const float*)d_in[2];
    const float* Wq = (const float*)d_in[4];
    const float* bq = (const float*)d_in[5];
    const float* Wk = (const float*)d_in[6];
    // d_in[7] = bk : enters only softmax-invariant terms -> dropped exactly
    const float* Wv = (const float*)d_in[8];
    const float* bv = (const float*)d_in[9];
    const float* Wo = (const float*)d_in[10];
    const float* bo = (const float*)d_in[11];
    float* out = (float*)d_out;

    __nv_bfloat16 *Qc, *Kc, *Vc, *WkT, *WqT, *WvT, *Wos, *H, *WvoB, *T, *Zt, *Pbf;
    float *Zf, *P, *w2, *cb, *vb;
    cudaGetSymbolAddress((void**)&Qc,  g_Qc);
    cudaGetSymbolAddress((void**)&Kc,  g_Kc);
    cudaGetSymbolAddress((void**)&Vc,  g_Vc);
    cudaGetSymbolAddress((void**)&WkT, g_WkT);
    cudaGetSymbolAddress((void**)&WqT, g_WqT);
    cudaGetSymbolAddress((void**)&WvT, g_WvT);
    cudaGetSymbolAddress((void**)&Wos, g_Wos);
    cudaGetSymbolAddress((void**)&H,   g_H);
    cudaGetSymbolAddress((void**)&WvoB,g_WvoB);
    cudaGetSymbolAddress((void**)&T,   g_T);
    cudaGetSymbolAddress((void**)&Zf,  g_Zf);
    cudaGetSymbolAddress((void**)&Zt,  g_Zt);
    cudaGetSymbolAddress((void**)&P,   g_P);
    cudaGetSymbolAddress((void**)&Pbf, g_Pbf);
    cudaGetSymbolAddress((void**)&w2,  g_w2);
    cudaGetSymbolAddress((void**)&cb,  g_cb);
    cudaGetSymbolAddress((void**)&vb,  g_vb);

    cudaFuncSetAttribute(gemm_dual1,
                         cudaFuncAttributeMaxDynamicSharedMemorySize, GEMM_SMEM);
    cudaFuncSetAttribute(gemm_one<1, false, false>,
                         cudaFuncAttributeMaxDynamicSharedMemorySize, GEMM_SMEM);
    cudaFuncSetAttribute(gemm_one<0, false, false>,
                         cudaFuncAttributeMaxDynamicSharedMemorySize, GEMM_SMEM);
    cudaFuncSetAttribute(gemm_one<4, false, true>,
                         cudaFuncAttributeMaxDynamicSharedMemorySize, GEMM_SMEM);
    cudaFuncSetAttribute(gemm_one<0, true, false>,
                         cudaFuncAttributeMaxDynamicSharedMemorySize, GEMM_SMEM);

    const long n4w = (long)D_ * D_ / 4;
    const long n4i = (long)M_ * D_ / 4;

    // ---- conversions ----
    conv_split_k1024<<<(unsigned)((n4i + 255) / 256), 256>>>(query, Qc, n4i);
    conv_split_k1024<<<(unsigned)((n4i + 255) / 256), 256>>>(key,   Kc, n4i);
    conv_split_k1024<<<(unsigned)((n4i + 255) / 256), 256>>>(value, Vc, n4i);
    conv_split_k1024<<<(unsigned)((n4w + 255) / 256), 256>>>(Wo, Wos, n4w);
    transpose_split_w<<<dim3(D_ / 32, D_ / 32), dim3(32, 8)>>>(Wk, WkT);
    transpose_split_w<<<dim3(D_ / 32, D_ / 32), dim3(32, 8)>>>(Wq, WqT);
    transpose_split_w<<<dim3(D_ / 32, D_ / 32), dim3(32, 8)>>>(Wv, WvT);

    // ---- exact bias terms ----
    w2_kernel<<<D_ / 256, 256>>>(Wk, bq, w2);
    cb_kernel<<<D_ / 8, 256>>>(Wo, bv, bo, cb);
    vb_kernel<<<M_ / 8, 256>>>(key, w2, vb);

    // ---- H = Wk^T Wq (rows=a)  and  WvoB = (Wo Wv)[o][a], one dual launch ----
    GArgs hA{};
    hA.A = WkT; hA.lda = 2 * D_; hA.bsA = 0; hA.oAlo = D_;
    hA.B = WqT; hA.ldb = 2 * D_; hA.bsB = 0; hA.oBlo = D_;
    hA.Kpart = D_; hA.scale = 1.0f; hA.bias = nullptr; hA.cbias = nullptr;
    hA.outH = H; hA.ldo = 2 * D_; hA.bsO = 0; hA.loOff = D_;
    GArgs hB = hA;
    hB.A = Wos; hB.B = WvT; hB.outH = WvoB;
    gemm_dual1<<<dim3(D_ / 128, D_ / 256, 2), 256, GEMM_SMEM>>>(hA, hB);

    // ---- T = query * G (split out) ----
    GArgs tA{};
    tA.A = Qc; tA.lda = 2 * D_; tA.bsA = 0; tA.oAlo = D_;
    tA.B = H;  tA.ldb = 2 * D_; tA.bsB = 0; tA.oBlo = D_;
    tA.Kpart = D_; tA.scale = 1.0f; tA.bias = nullptr; tA.cbias = nullptr;
    tA.outH = T; tA.ldo = 2 * D_; tA.bsO = 0; tA.loOff = D_;
    gemm_one<1, false, false><<<dim3(D_ / 128, M_ / 256, 1), 256, GEMM_SMEM>>>(tA);

    // ---- Z = value * Wvo^T (fp32 out) ----
    GArgs tB{};
    tB.A = Vc; tB.lda = 2 * D_; tB.bsA = 0; tB.oAlo = D_;
    tB.B = WvoB; tB.ldb = 2 * D_; tB.bsB = 0; tB.oBlo = D_;
    tB.Kpart = D_; tB.scale = 1.0f; tB.bias = nullptr; tB.cbias = nullptr;
    tB.outF = Zf; tB.ldo = D_; tB.bsO = 0;
    gemm_one<0, false, false><<<dim3(D_ / 128, M_ / 256, 1), 256, GEMM_SMEM>>>(tB);

    // ---- Z^T split for the PV GEMM ----
    transpose_split_v<<<dim3(D_ / 32, S_ / 32, B_), dim3(32, 8)>>>(Zf, Zt);

    // ---- Scores: P = SCALE * (T . key^T + vb), tril tiles, causal mask ----
    GArgs sc{};
    sc.A = T;  sc.lda = (long)B_ * 2 * D_; sc.bsA = 2 * D_; sc.oAlo = D_;
    sc.B = Kc; sc.ldb = (long)B_ * 2 * D_; sc.bsB = 2 * D_; sc.oBlo = D_;
    sc.Kpart = D_; sc.scale = SCALE_; sc.bias = nullptr; sc.cbias = vb;
    sc.outF = P; sc.ldo = S_; sc.bsO = (long)S_ * S_;
    gemm_one<4, false, true><<<dim3(S_ / 128, S_ / 256, B_), 256, GEMM_SMEM>>>(sc);

    // ---- fused softmax + P split ----
    softmax_split<<<dim3(S_, B_), 256>>>(P, Pbf);

    // ---- out = P @ Z + cb (causal K bound), fp32 straight to d_out ----
    GArgs pv{};
    pv.A = Pbf; pv.lda = 2 * S_; pv.bsA = (long)S_ * 2 * S_; pv.oAlo = S_;
    pv.B = Zt;  pv.ldb = 2 * S_; pv.bsB = (long)D_ * 2 * S_; pv.oBlo = S_;
    pv.Kpart = S_; pv.scale = 1.0f; pv.bias = cb; pv.cbias = nullptr;
    pv.outF = out; pv.ldo = (long)B_ * D_; pv.bsO = D_;
    gemm_one<0, true, false><<<dim3(D_ / 128, S_ / 256, B_), 256, GEMM_SMEM>>>(pv);
}

// round 10
// speedup vs baseline: 1.5510x; 1.0747x over previous
#include <cuda_runtime.h>
#include <cuda_bf16.h>
#include <cstdint>
#include <math.h>

// ---------------------------------------------------------------------------
// Problem constants
// ---------------------------------------------------------------------------
static constexpr int S_ = 2048, B_ = 8, D_ = 1024, M_ = S_ * B_;
static constexpr float SCALE_ = 0.03125f;  // 1/sqrt(1024)

// ---------------------------------------------------------------------------
// Static scratch. Split-bf16 layout: row-major [rows][2*K]: hi at [k], lo at [K+k].
// ---------------------------------------------------------------------------
__device__ __nv_bfloat16 g_Qc [(size_t)M_ * 2 * D_];
__device__ __nv_bfloat16 g_Kc [(size_t)M_ * 2 * D_];
__device__ __nv_bfloat16 g_Vc [(size_t)M_ * 2 * D_];
__device__ __nv_bfloat16 g_WkT[(size_t)D_ * 2 * D_];
__device__ __nv_bfloat16 g_WqT[(size_t)D_ * 2 * D_];
__device__ __nv_bfloat16 g_WvT[(size_t)D_ * 2 * D_];
__device__ __nv_bfloat16 g_Wos[(size_t)D_ * 2 * D_];
__device__ __nv_bfloat16 g_H  [(size_t)D_ * 2 * D_];   // (Wk^T Wq) split
__device__ __nv_bfloat16 g_WvoB[(size_t)D_ * 2 * D_];  // (Wo Wv)[o][a] split
__device__ __nv_bfloat16 g_T  [(size_t)M_ * 2 * D_];   // T = query * G
__device__ float         g_Zf [(size_t)M_ * D_];       // Z = value * Wvo^T
__device__ __nv_bfloat16 g_Zt [(size_t)B_ * D_ * 2 * S_]; // Z^T split
__device__ float         g_P  [(size_t)B_ * S_ * S_];
__device__ __nv_bfloat16 g_Pbf[(size_t)B_ * S_ * 2 * S_];
__device__ float         g_w2 [D_];
__device__ float         g_cb [D_];
__device__ float         g_vb [(size_t)B_ * S_];

// ---------------------------------------------------------------------------
// Portable PTX helpers
// ---------------------------------------------------------------------------
__device__ __forceinline__ uint32_t smem_u32(const void* p) {
    uint32_t a;
    asm("{ .reg .u64 t; cvta.to.shared.u64 t, %1; cvt.u32.u64 %0, t; }" : "=r"(a) : "l"(p));
    return a;
}

__device__ __forceinline__ void ldsm4(uint32_t* r, uint32_t a) {
    asm volatile("ldmatrix.sync.aligned.m8n8.x4.shared.b16 {%0,%1,%2,%3}, [%4];"
                 : "=r"(r[0]), "=r"(r[1]), "=r"(r[2]), "=r"(r[3]) : "r"(a));
}

__device__ __forceinline__ void mma16816(float* d, const uint32_t* a, const uint32_t* b) {
    asm volatile(
        "mma.sync.aligned.m16n8k16.row.col.f32.bf16.bf16.f32 "
        "{%0,%1,%2,%3}, {%4,%5,%6,%7}, {%8,%9}, {%0,%1,%2,%3};"
        : "+f"(d[0]), "+f"(d[1]), "+f"(d[2]), "+f"(d[3])
        : "r"(a[0]), "r"(a[1]), "r"(a[2]), "r"(a[3]), "r"(b[0]), "r"(b[1]));
}

__device__ __forceinline__ void cp16(uint32_t saddr, const void* gaddr) {
    asm volatile("cp.async.cg.shared.global [%0], [%1], 16;" :: "r"(saddr), "l"(gaddr));
}
__device__ __forceinline__ void cp_commit() {
    asm volatile("cp.async.commit_group;" ::: "memory");
}
template<int N>
__device__ __forceinline__ void cp_wait() {
    asm volatile("cp.async.wait_group %0;" :: "n"(N) : "memory");
}

__device__ __forceinline__ float neg_inf_f() { return __int_as_float(0xff800000); }

__device__ __forceinline__ uint32_t pack_bf2(float a, float b) {
    __nv_bfloat162 h = __floats2bfloat162_rn(a, b);
    return *reinterpret_cast<uint32_t*>(&h);
}

// ---------------------------------------------------------------------------
// Fused split GEMM body (identical engine to R9 winner).
// EPI: 0 = fp32 out (+bias), 1 = split-bf16 out, 4 = scores (cbias+mask+scale)
// ---------------------------------------------------------------------------
struct GArgs {
    const __nv_bfloat16* A; const __nv_bfloat16* B;
    long lda, ldb, bsA, bsB;
    long oAlo, oBlo;
    int  Kpart;
    float scale;
    const float* bias;
    const float* cbias;
    float* outF;
    __nv_bfloat16* outH;
    long ldo, bsO, loOff;
};

static constexpr int A_TILE = 32768;
static constexpr int B_TILE = 16384;
static constexpr int STAGE  = 2 * A_TILE + 2 * B_TILE;  // 96 KB
static constexpr int GEMM_SMEM = 1024 + 2 * STAGE;      // 193 KB

template<int EPI, bool CAUSALK, bool TRIL>
__device__ __forceinline__ void gemm_body(const GArgs& g, int nt, int mt, int bz)
{
    if (TRIL && nt * 128 > mt * 256 + 255) return;
    const int mBase = mt * 256, nBase = nt * 128;

    extern __shared__ char smem_raw[];
    const uint32_t sbase = smem_u32(smem_raw);
    const uint32_t abase = (sbase + 1023) & ~1023u;

    const int tid  = threadIdx.x;
    const int lane = tid & 31;
    const int warp = tid >> 5;
    const int wm   = warp >> 1;
    const int wn   = warp & 1;

    const __nv_bfloat16* Ab = g.A + (long)bz * g.bsA;
    const __nv_bfloat16* Bb = g.B + (long)bz * g.bsB;

    const int kEff = CAUSALK ? (mBase + 256) : g.Kpart;
    const int nch  = kEff >> 6;

    auto issue_chunk = [&](int c) {
        const long kc = (long)(c << 6);
        const int st = c & 1;
        const uint32_t sAhi = abase + st * STAGE;
        const uint32_t sAlo = sAhi + A_TILE;
        const uint32_t sBhi = sAhi + 2 * A_TILE;
        const uint32_t sBlo = sBhi + B_TILE;
#pragma unroll
        for (int i = 0; i < 8; i++) {
            const int id = tid + i * 256;
            const int row = id >> 3, cc = id & 7;
            const uint32_t so = (uint32_t)(row << 7) + (uint32_t)((cc ^ (row & 7)) << 4);
            const __nv_bfloat16* src = Ab + (long)(mBase + row) * g.lda + kc + cc * 8;
            cp16(sAhi + so, src);
            cp16(sAlo + so, src + g.oAlo);
        }
#pragma unroll
        for (int i = 0; i < 4; i++) {
            const int id = tid + i * 256;
            const int row = id >> 3, cc = id & 7;
            const uint32_t so = (uint32_t)(row << 7) + (uint32_t)((cc ^ (row & 7)) << 4);
            const __nv_bfloat16* src = Bb + (long)(nBase + row) * g.ldb + kc + cc * 8;
            cp16(sBhi + so, src);
            cp16(sBlo + so, src + g.oBlo);
        }
        cp_commit();
    };

    float acc[4][8][4];
#pragma unroll
    for (int i = 0; i < 4; i++)
#pragma unroll
        for (int j = 0; j < 8; j++)
#pragma unroll
            for (int d = 0; d < 4; d++) acc[i][j][d] = 0.0f;

    issue_chunk(0);

    const int arow = (lane & 7) + ((lane >> 3) & 1) * 8;
    const int acol = lane >> 4;
    const int brow = (lane & 7) + ((lane >> 4) & 1) * 8;
    const int bcol = (lane >> 3) & 1;

    for (int c = 0; c < nch; c++) {
        if (c + 1 < nch) issue_chunk(c + 1);
        if (c + 1 < nch) cp_wait<1>(); else cp_wait<0>();
        __syncthreads();

        const int st = c & 1;
        const uint32_t sAhi = abase + st * STAGE;
        const uint32_t sAlo = sAhi + A_TILE;
        const uint32_t sBhi = sAhi + 2 * A_TILE;
        const uint32_t sBlo = sBhi + B_TILE;

#pragma unroll
        for (int ks = 0; ks < 4; ks++) {
            uint32_t af[4][4], bf[4][4];
            // pass 1: Alo x Bhi
#pragma unroll
            for (int mi = 0; mi < 4; mi++) {
                const int row = wm * 64 + mi * 16 + arow;
                const int cc  = ks * 2 + acol;
                ldsm4(af[mi], sAlo + (row << 7) + ((cc ^ (row & 7)) << 4));
            }
#pragma unroll
            for (int nj = 0; nj < 4; nj++) {
                const int row = wn * 64 + nj * 16 + brow;
                const int cc  = ks * 2 + bcol;
                ldsm4(bf[nj], sBhi + (row << 7) + ((cc ^ (row & 7)) << 4));
            }
#pragma unroll
            for (int mi = 0; mi < 4; mi++)
#pragma unroll
                for (int nj = 0; nj < 4; nj++) {
                    mma16816(acc[mi][2 * nj],     af[mi], &bf[nj][0]);
                    mma16816(acc[mi][2 * nj + 1], af[mi], &bf[nj][2]);
                }
            // pass 2: Ahi x Bhi
#pragma unroll
            for (int mi = 0; mi < 4; mi++) {
                const int row = wm * 64 + mi * 16 + arow;
                const int cc  = ks * 2 + acol;
                ldsm4(af[mi], sAhi + (row << 7) + ((cc ^ (row & 7)) << 4));
            }
#pragma unroll
            for (int mi = 0; mi < 4; mi++)
#pragma unroll
                for (int nj = 0; nj < 4; nj++) {
                    mma16816(acc[mi][2 * nj],     af[mi], &bf[nj][0]);
                    mma16816(acc[mi][2 * nj + 1], af[mi], &bf[nj][2]);
                }
            // pass 3: Ahi x Blo
#pragma unroll
            for (int nj = 0; nj < 4; nj++) {
                const int row = wn * 64 + nj * 16 + brow;
                const int cc  = ks * 2 + bcol;
                ldsm4(bf[nj], sBlo + (row << 7) + ((cc ^ (row & 7)) << 4));
            }
#pragma unroll
            for (int mi = 0; mi < 4; mi++)
#pragma unroll
                for (int nj = 0; nj < 4; nj++) {
                    mma16816(acc[mi][2 * nj],     af[mi], &bf[nj][0]);
                    mma16816(acc[mi][2 * nj + 1], af[mi], &bf[nj][2]);
                }
        }
        __syncthreads();
    }

    // ------------------------- epilogue (compile-time EPI) -------------------
    const int gq = lane >> 2, tg = lane & 3;
#pragma unroll
    for (int mi = 0; mi < 4; mi++) {
#pragma unroll
        for (int half = 0; half < 2; half++) {
            const int gm = mBase + wm * 64 + mi * 16 + gq + half * 8;
#pragma unroll
            for (int ni = 0; ni < 8; ni++) {
                const int gn = nBase + wn * 64 + ni * 8 + 2 * tg;
                const float v0 = acc[mi][ni][half * 2 + 0];
                const float v1 = acc[mi][ni][half * 2 + 1];

                if (EPI == 0) {
                    float2 v;
                    v.x = v0; v.y = v1;
                    if (g.bias) { v.x += g.bias[gn + 0]; v.y += g.bias[gn + 1]; }
                    *reinterpret_cast<float2*>(
                        g.outF + (long)bz * g.bsO + (long)gm * g.ldo + gn) = v;
                } else if (EPI == 1) {
                    const __nv_bfloat16 h0 = __float2bfloat16(v0);
                    const __nv_bfloat16 h1 = __float2bfloat16(v1);
                    const __nv_bfloat16 l0 = __float2bfloat16(v0 - __bfloat162float(h0));
                    const __nv_bfloat16 l1 = __float2bfloat16(v1 - __bfloat162float(h1));
                    __nv_bfloat16* o = g.outH + (long)bz * g.bsO + (long)gm * g.ldo + gn;
                    *reinterpret_cast<__nv_bfloat162*>(o) = __nv_bfloat162(h0, h1);
                    *reinterpret_cast<__nv_bfloat162*>(o + g.loOff) = __nv_bfloat162(l0, l1);
                } else {  // EPI == 4 : scores
                    const float cb0 = g.cbias[(long)bz * S_ + gn + 0];
                    const float cb1 = g.cbias[(long)bz * S_ + gn + 1];
                    float2 v;
                    v.x = (gn + 0 > gm) ? neg_inf_f() : (v0 + cb0) * g.scale;
                    v.y = (gn + 1 > gm) ? neg_inf_f() : (v1 + cb1) * g.scale;
                    *reinterpret_cast<float2*>(
                        g.outF + (long)bz * g.bsO + (long)gm * g.ldo + gn) = v;
                }
            }
        }
    }
}

// Single GEMM; heavy (high-mt) tiles scheduled first via reversed mt.
template<int EPI, bool CAUSALK, bool TRIL>
__global__ void __launch_bounds__(256, 1) gemm_one(GArgs g)
{
    gemm_body<EPI, CAUSALK, TRIL>(g, blockIdx.x, gridDim.y - 1 - blockIdx.y, blockIdx.z);
}

// Two GEMMs in one launch with compile-time EPIs picked by blockIdx.z.
template<int E0, int E1>
__global__ void __launch_bounds__(256, 1) gemm_dual(GArgs g0, GArgs g1)
{
    if (blockIdx.z == 0)
        gemm_body<E0, false, false>(g0, blockIdx.x, blockIdx.y, 0);
    else
        gemm_body<E1, false, false>(g1, blockIdx.x, blockIdx.y, 0);
}

// ---------------------------------------------------------------------------
// Merged q/k/v fp32 -> split bf16 [m][2*1024]; 4 float4s per thread (MLP=4)
// ---------------------------------------------------------------------------
__global__ void conv_split_in(const float* __restrict__ q, const float* __restrict__ k,
                              const float* __restrict__ v,
                              __nv_bfloat16* __restrict__ Qc, __nv_bfloat16* __restrict__ Kc,
                              __nv_bfloat16* __restrict__ Vc)
{
    const float* in = (blockIdx.z == 0) ? q : (blockIdx.z == 1) ? k : v;
    __nv_bfloat16* out = (blockIdx.z == 0) ? Qc : (blockIdx.z == 1) ? Kc : Vc;
    const long base = (long)blockIdx.x * 1024 + threadIdx.x;

    float4 v4[4];
#pragma unroll
    for (int j = 0; j < 4; j++)
        v4[j] = reinterpret_cast<const float4*>(in)[base + j * 256];

#pragma unroll
    for (int j = 0; j < 4; j++) {
        const long idx = (base + j * 256) * 4;
        const long m = idx >> 10;
        const int  kk = (int)(idx & 1023);
        const __nv_bfloat16 h0 = __float2bfloat16(v4[j].x);
        const __nv_bfloat16 h1 = __float2bfloat16(v4[j].y);
        const __nv_bfloat16 h2 = __float2bfloat16(v4[j].z);
        const __nv_bfloat16 h3 = __float2bfloat16(v4[j].w);
        uint2 hp, lp;
        hp.x = pack_bf2(v4[j].x, v4[j].y);
        hp.y = pack_bf2(v4[j].z, v4[j].w);
        lp.x = pack_bf2(v4[j].x - __bfloat162float(h0), v4[j].y - __bfloat162float(h1));
        lp.y = pack_bf2(v4[j].z - __bfloat162float(h2), v4[j].w - __bfloat162float(h3));
        __nv_bfloat16* o = out + m * 2048 + kk;
        *reinterpret_cast<uint2*>(o)        = hp;
        *reinterpret_cast<uint2*>(o + 1024) = lp;
    }
}

// ---------------------------------------------------------------------------
// Weight fp32 -> split bf16 (row-major), 1 float4 per thread (small)
// ---------------------------------------------------------------------------
__global__ void conv_split_k1024(const float* __restrict__ in,
                                 __nv_bfloat16* __restrict__ out, long n4)
{
    const long i = (long)blockIdx.x * 256 + threadIdx.x;
    if (i >= n4) return;
    const float4 v = reinterpret_cast<const float4*>(in)[i];
    const long idx = i * 4;
    const long m = idx >> 10;
    const int  k = (int)(idx & 1023);
    const __nv_bfloat16 h0 = __float2bfloat16(v.x);
    const __nv_bfloat16 h1 = __float2bfloat16(v.y);
    const __nv_bfloat16 h2 = __float2bfloat16(v.z);
    const __nv_bfloat16 h3 = __float2bfloat16(v.w);
    uint2 hp, lp;
    hp.x = pack_bf2(v.x, v.y);
    hp.y = pack_bf2(v.z, v.w);
    lp.x = pack_bf2(v.x - __bfloat162float(h0), v.y - __bfloat162float(h1));
    lp.y = pack_bf2(v.z - __bfloat162float(h2), v.w - __bfloat162float(h3));
    __nv_bfloat16* o = out + m * 2048 + k;
    *reinterpret_cast<uint2*>(o)        = hp;
    *reinterpret_cast<uint2*>(o + 1024) = lp;
}

// ---------------------------------------------------------------------------
// Weight transpose + split: out[a][e](hi/lo) = W[e][a]
// ---------------------------------------------------------------------------
__global__ void transpose_split_w(const float* __restrict__ W,
                                  __nv_bfloat16* __restrict__ out)
{
    __shared__ float t[32][33];
    const int a0 = blockIdx.x * 32, e0 = blockIdx.y * 32;
    const int tx = threadIdx.x, ty = threadIdx.y;
#pragma unroll
    for (int r = 0; r < 32; r += 8)
        t[r + ty][tx] = W[(long)(e0 + r + ty) * D_ + a0 + tx];
    __syncthreads();
#pragma unroll
    for (int r = 0; r < 32; r += 8) {
        const int a = a0 + r + ty, e = e0 + tx;
        const float v = t[tx][r + ty];
        const __nv_bfloat16 h = __float2bfloat16(v);
        __nv_bfloat16* o = out + (long)a * 2 * D_ + e;
        o[0]  = h;
        o[D_] = __float2bfloat16(v - __bfloat162float(h));
    }
}

// ---------------------------------------------------------------------------
// Z fp32 [s*B+b][d] -> Zt split [b][d][hi(S)|lo(S)], packed uint32 stores.
// Tile: 64 s x 32 d, block (32, 8).
// ---------------------------------------------------------------------------
__global__ void transpose_split_v(const float* __restrict__ Vf,
                                  __nv_bfloat16* __restrict__ Vt)
{
    __shared__ float t[64][33];
    const int d0 = blockIdx.x * 32, s0 = blockIdx.y * 64, b = blockIdx.z;
    const int tx = threadIdx.x, ty = threadIdx.y;
#pragma unroll
    for (int j = 0; j < 8; j++) {
        const int sl = j * 8 + ty;
        t[sl][tx] = Vf[((size_t)(s0 + sl) * B_ + b) * D_ + d0 + tx];
    }
    __syncthreads();
#pragma unroll
    for (int jj = 0; jj < 4; jj++) {
        const int dl = jj * 8 + ty;
        const float va = t[2 * tx][dl];
        const float vb = t[2 * tx + 1][dl];
        const __nv_bfloat16 ha = __float2bfloat16(va);
        const __nv_bfloat16 hb = __float2bfloat16(vb);
        __nv_bfloat16* o = Vt + ((size_t)b * D_ + d0 + dl) * (2 * S_) + s0 + 2 * tx;
        *reinterpret_cast<uint32_t*>(o) = pack_bf2(va, vb);
        *reinterpret_cast<uint32_t*>(o + S_) =
            pack_bf2(va - __bfloat162float(ha), vb - __bfloat162float(hb));
    }
}

// ---------------------------------------------------------------------------
// Small exact-bias kernels
// ---------------------------------------------------------------------------
__global__ void w2_kernel(const float* __restrict__ Wk, const float* __restrict__ bq,
                          float* __restrict__ w2)
{
    const int a = blockIdx.x * 256 + threadIdx.x;
    float s = 0.0f;
    for (int d = 0; d < D_; d++) s += bq[d] * Wk[(long)d * D_ + a];
    w2[a] = s;
}

__global__ void cb_kernel(const float* __restrict__ Wo, const float* __restrict__ bv,
                          const float* __restrict__ bo, float* __restrict__ cb)
{
    const int o = blockIdx.x * 8 + (threadIdx.x >> 5);
    const int lane = threadIdx.x & 31;
    float s = 0.0f;
    for (int e = lane * 4; e < D_; e += 128) {
        const float4 w = *reinterpret_cast<const float4*>(Wo + (long)o * D_ + e);
        const float4 b = *reinterpret_cast<const float4*>(bv + e);
        s += w.x * b.x + w.y * b.y + w.z * b.z + w.w * b.w;
    }
#pragma unroll
    for (int off = 16; off > 0; off >>= 1) s += __shfl_xor_sync(0xffffffffu, s, off);
    if (lane == 0) cb[o] = bo[o] + s;
}

__global__ void vb_kernel(const float* __restrict__ key, const float* __restrict__ w2,
                          float* __restrict__ vb)
{
    const int m = blockIdx.x * 8 + (threadIdx.x >> 5);
    const int lane = threadIdx.x & 31;
    const float* row = key + (long)m * D_;
    float s = 0.0f;
    for (int a = lane * 4; a < D_; a += 128) {
        const float4 k = *reinterpret_cast<const float4*>(row + a);
        const float4 w = *reinterpret_cast<const float4*>(w2 + a);
        s += k.x * w.x + k.y * w.y + k.z * w.z + k.w * w.w;
    }
#pragma unroll
    for (int off = 16; off > 0; off >>= 1) s += __shfl_xor_sync(0xffffffffu, s, off);
    if (lane == 0) {
        const int b = m & (B_ - 1);
        const int j = m >> 3;
        vb[(long)b * S_ + j] = s;
    }
}

// ---------------------------------------------------------------------------
// Fused row softmax + split-bf16 emit (fast exp, float4 strides)
// ---------------------------------------------------------------------------
__global__ void __launch_bounds__(256) softmax_split(const float* __restrict__ P,
                                                     __nv_bfloat16* __restrict__ Pb)
{
    const int i = blockIdx.x, b = blockIdx.y;
    const float* p = P + ((size_t)b * S_ + i) * S_;
    __nv_bfloat16* o = Pb + ((size_t)b * S_ + i) * (2 * S_);
    const int jEnd = ((i >> 7) + 1) << 7;
    const int tid = threadIdx.x;
    __shared__ float sm[8];

    float m = neg_inf_f();
    for (int j = tid * 4; j < jEnd; j += 1024) {
        const float4 v = *reinterpret_cast<const float4*>(p + j);
        m = fmaxf(m, fmaxf(fmaxf(v.x, v.y), fmaxf(v.z, v.w)));
    }
#pragma unroll
    for (int off = 16; off > 0; off >>= 1) m = fmaxf(m, __shfl_xor_sync(0xffffffffu, m, off));
    if ((tid & 31) == 0) sm[tid >> 5] = m;
    __syncthreads();
    const float rowmax = fmaxf(fmaxf(fmaxf(sm[0], sm[1]), fmaxf(sm[2], sm[3])),
                               fmaxf(fmaxf(sm[4], sm[5]), fmaxf(sm[6], sm[7])));
    __syncthreads();

    float s = 0.0f;
    for (int j = tid * 4; j < jEnd; j += 1024) {
        const float4 v = *reinterpret_cast<const float4*>(p + j);
        s += __expf(v.x - rowmax) + __expf(v.y - rowmax)
           + __expf(v.z - rowmax) + __expf(v.w - rowmax);
    }
#pragma unroll
    for (int off = 16; off > 0; off >>= 1) s += __shfl_xor_sync(0xffffffffu, s, off);
    if ((tid & 31) == 0) sm[tid >> 5] = s;
    __syncthreads();
    const float inv = 1.0f / ((sm[0] + sm[1]) + (sm[2] + sm[3]) + (sm[4] + sm[5]) + (sm[6] + sm[7]));

    for (int j = tid * 4; j < jEnd; j += 1024) {
        const float4 v = *reinterpret_cast<const float4*>(p + j);
        const float e0 = __expf(v.x - rowmax) * inv;
        const float e1 = __expf(v.y - rowmax) * inv;
        const float e2 = __expf(v.z - rowmax) * inv;
        const float e3 = __expf(v.w - rowmax) * inv;
        const __nv_bfloat16 h0 = __float2bfloat16(e0);
        const __nv_bfloat16 h1 = __float2bfloat16(e1);
        const __nv_bfloat16 h2 = __float2bfloat16(e2);
        const __nv_bfloat16 h3 = __float2bfloat16(e3);
        uint2 hp, lp;
        hp.x = pack_bf2(e0, e1); hp.y = pack_bf2(e2, e3);
        lp.x = pack_bf2(e0 - __bfloat162float(h0), e1 - __bfloat162float(h1));
        lp.y = pack_bf2(e2 - __bfloat162float(h2), e3 - __bfloat162float(h3));
        *reinterpret_cast<uint2*>(o + j)      = hp;
        *reinterpret_cast<uint2*>(o + S_ + j) = lp;
    }
}

// ---------------------------------------------------------------------------
extern "C" void kernel_launch(void* const* d_in, const int* in_sizes, int n_in,
                              void* d_out, int out_size)
{
    const float* query = (const float*)d_in[0];
    const float* key   = (const float*)d_in[1];
    const float* value = (const float*)d_in[2];
    const float* Wq = (const float*)d_in[4];
    const float* bq = (const float*)d_in[5];
    const float* Wk = (const float*)d_in[6];
    // d_in[7] = bk : softmax-invariant, dropped exactly
    const float* Wv = (const float*)d_in[8];
    const float* bv = (const float*)d_in[9];
    const float* Wo = (const float*)d_in[10];
    const float* bo = (const float*)d_in[11];
    float* out = (float*)d_out;

    __nv_bfloat16 *Qc, *Kc, *Vc, *WkT, *WqT, *WvT, *Wos, *H, *WvoB, *T, *Zt, *Pbf;
    float *Zf, *P, *w2, *cb, *vb;
    cudaGetSymbolAddress((void**)&Qc,  g_Qc);
    cudaGetSymbolAddress((void**)&Kc,  g_Kc);
    cudaGetSymbolAddress((void**)&Vc,  g_Vc);
    cudaGetSymbolAddress((void**)&WkT, g_WkT);
    cudaGetSymbolAddress((void**)&WqT, g_WqT);
    cudaGetSymbolAddress((void**)&WvT, g_WvT);
    cudaGetSymbolAddress((void**)&Wos, g_Wos);
    cudaGetSymbolAddress((void**)&H,   g_H);
    cudaGetSymbolAddress((void**)&WvoB,g_WvoB);
    cudaGetSymbolAddress((void**)&T,   g_T);
    cudaGetSymbolAddress((void**)&Zf,  g_Zf);
    cudaGetSymbolAddress((void**)&Zt,  g_Zt);
    cudaGetSymbolAddress((void**)&P,   g_P);
    cudaGetSymbolAddress((void**)&Pbf, g_Pbf);
    cudaGetSymbolAddress((void**)&w2,  g_w2);
    cudaGetSymbolAddress((void**)&cb,  g_cb);
    cudaGetSymbolAddress((void**)&vb,  g_vb);

    cudaFuncSetAttribute(gemm_dual<1, 1>,
                         cudaFuncAttributeMaxDynamicSharedMemorySize, GEMM_SMEM);
    cudaFuncSetAttribute(gemm_dual<1, 0>,
                         cudaFuncAttributeMaxDynamicSharedMemorySize, GEMM_SMEM);
    cudaFuncSetAttribute(gemm_one<4, false, true>,
                         cudaFuncAttributeMaxDynamicSharedMemorySize, GEMM_SMEM);
    cudaFuncSetAttribute(gemm_one<0, true, false>,
                         cudaFuncAttributeMaxDynamicSharedMemorySize, GEMM_SMEM);

    const long n4w = (long)D_ * D_ / 4;
    const long n4i = (long)M_ * D_ / 4;

    // ---- conversions (q/k/v merged, MLP=4) ----
    conv_split_in<<<dim3((unsigned)(n4i / 1024), 1, 3), 256>>>(query, key, value, Qc, Kc, Vc);
    conv_split_k1024<<<(unsigned)((n4w + 255) / 256), 256>>>(Wo, Wos, n4w);
    transpose_split_w<<<dim3(D_ / 32, D_ / 32), dim3(32, 8)>>>(Wk, WkT);
    transpose_split_w<<<dim3(D_ / 32, D_ / 32), dim3(32, 8)>>>(Wq, WqT);
    transpose_split_w<<<dim3(D_ / 32, D_ / 32), dim3(32, 8)>>>(Wv, WvT);

    // ---- exact bias terms ----
    w2_kernel<<<D_ / 256, 256>>>(Wk, bq, w2);
    cb_kernel<<<D_ / 8, 256>>>(Wo, bv, bo, cb);
    vb_kernel<<<M_ / 8, 256>>>(key, w2, vb);

    // ---- H = Wk^T Wq  and  WvoB = (Wo Wv)[o][a], one dual launch ----
    GArgs hA{};
    hA.A = WkT; hA.lda = 2 * D_; hA.bsA = 0; hA.oAlo = D_;
    hA.B = WqT; hA.ldb = 2 * D_; hA.bsB = 0; hA.oBlo = D_;
    hA.Kpart = D_; hA.scale = 1.0f; hA.bias = nullptr; hA.cbias = nullptr;
    hA.outH = H; hA.ldo = 2 * D_; hA.bsO = 0; hA.loOff = D_;
    GArgs hB = hA;
    hB.A = Wos; hB.B = WvT; hB.outH = WvoB;
    gemm_dual<1, 1><<<dim3(D_ / 128, D_ / 256, 2), 256, GEMM_SMEM>>>(hA, hB);

    // ---- T = query * G (split out)  and  Z = value * Wvo^T (fp32 out), dual ----
    GArgs tA{};
    tA.A = Qc; tA.lda = 2 * D_; tA.bsA = 0; tA.oAlo = D_;
    tA.B = H;  tA.ldb = 2 * D_; tA.bsB = 0; tA.oBlo = D_;
    tA.Kpart = D_; tA.scale = 1.0f; tA.bias = nullptr; tA.cbias = nullptr;
    tA.outH = T; tA.ldo = 2 * D_; tA.bsO = 0; tA.loOff = D_;
    GArgs tB{};
    tB.A = Vc; tB.lda = 2 * D_; tB.bsA = 0; tB.oAlo = D_;
    tB.B = WvoB; tB.ldb = 2 * D_; tB.bsB = 0; tB.oBlo = D_;
    tB.Kpart = D_; tB.scale = 1.0f; tB.bias = nullptr; tB.cbias = nullptr;
    tB.outF = Zf; tB.ldo = D_; tB.bsO = 0;
    gemm_dual<1, 0><<<dim3(D_ / 128, M_ / 256, 2), 256, GEMM_SMEM>>>(tA, tB);

    // ---- Z^T split for the PV GEMM ----
    transpose_split_v<<<dim3(D_ / 32, S_ / 64, B_), dim3(32, 8)>>>(Zf, Zt);

    // ---- Scores: P = SCALE * (T . key^T + vb), tril tiles, causal mask ----
    GArgs sc{};
    sc.A = T;  sc.lda = (long)B_ * 2 * D_; sc.bsA = 2 * D_; sc.oAlo = D_;
    sc.B = Kc; sc.ldb = (long)B_ * 2 * D_; sc.bsB = 2 * D_; sc.oBlo = D_;
    sc.Kpart = D_; sc.scale = SCALE_; sc.bias = nullptr; sc.cbias = vb;
    sc.outF = P; sc.ldo = S_; sc.bsO = (long)S_ * S_;
    gemm_one<4, false, true><<<dim3(S_ / 128, S_ / 256, B_), 256, GEMM_SMEM>>>(sc);

    // ---- fused softmax + P split ----
    softmax_split<<<dim3(S_, B_), 256>>>(P, Pbf);

    // ---- out = P @ Z + cb (causal K bound), fp32 straight to d_out ----
    GArgs pv{};
    pv.A = Pbf; pv.lda = 2 * S_; pv.bsA = (long)S_ * 2 * S_; pv.oAlo = S_;
    pv.B = Zt;  pv.ldb = 2 * S_; pv.bsB = (long)D_ * 2 * S_; pv.oBlo = S_;
    pv.Kpart = S_; pv.scale = 1.0f; pv.bias = cb; pv.cbias = nullptr;
    pv.outF = out; pv.ldo = (long)B_ * D_; pv.bsO = D_;
    gemm_one<0, true, false><<<dim3(D_ / 128, S_ / 256, B_), 256, GEMM_SMEM>>>(pv);
}